// round 16
// baseline (speedup 1.0000x reference)
#include <cuda_runtime.h>
#include <cuda_fp16.h>
#include <cstdint>

#define BATCH 32
#define NDIM  768
#define MTOT  (BATCH * NDIM)     // 24576
#define BK    64
#define NKT1  (NDIM / BK)        // 12 (aggx)
#define NKT_T (1536 / BK)        // 24 (biggemm, K=1536)
#define SXY   1536               // row stride of [X | Y]

// ---------------------------------------------------------------------------
// Scratch (fp16)
// ---------------------------------------------------------------------------
__device__ __half g_XY  [(size_t)MTOT * SXY];          // [X | Y] per row
__device__ __half g_Wcat[(size_t)1536 * NDIM];         // [W_l ; W_l1]
__device__ __half g_Adj [(size_t)BATCH * NDIM * NDIM]; // adj * rinv

// ---------------------------------------------------------------------------
// smem geometry: BK=64 stages
// ---------------------------------------------------------------------------
#define APAD 72                            // 64 k + 8 pad (row 144B, conflict-free)
#define BPAD 136
#define A_BYTES (128 * APAD * 2)           // 18432
#define B_BYTES (BK * BPAD * 2)            // 17408
#define S_AHI 0
#define S_BHI (A_BYTES)
#define S_BYTES (A_BYTES + B_BYTES)        // 35840
#define SMEM_G (3 * S_BYTES)               // 107520 -> 2 CTAs/SM (215KB)

// ---------------------------------------------------------------------------
// PTX helpers
// ---------------------------------------------------------------------------
__device__ __forceinline__ uint32_t smem_u32(const void* p) {
    uint32_t a;
    asm("{ .reg .u64 t; cvta.to.shared.u64 t, %1; cvt.u32.u64 %0, t; }" : "=r"(a) : "l"(p));
    return a;
}
__device__ __forceinline__ void ldsm4(uint32_t* r, uint32_t addr) {
    asm volatile("ldmatrix.sync.aligned.m8n8.x4.shared.b16 {%0,%1,%2,%3}, [%4];"
                 : "=r"(r[0]), "=r"(r[1]), "=r"(r[2]), "=r"(r[3]) : "r"(addr));
}
__device__ __forceinline__ void ldsm4t(uint32_t* r, uint32_t addr) {
    asm volatile("ldmatrix.sync.aligned.m8n8.x4.trans.shared.b16 {%0,%1,%2,%3}, [%4];"
                 : "=r"(r[0]), "=r"(r[1]), "=r"(r[2]), "=r"(r[3]) : "r"(addr));
}
__device__ __forceinline__ void hmma_f16(float* d, const uint32_t* a, const uint32_t* b) {
    asm volatile("mma.sync.aligned.m16n8k16.row.col.f32.f16.f16.f32 "
                 "{%0,%1,%2,%3}, {%4,%5,%6,%7}, {%8,%9}, {%0,%1,%2,%3};"
                 : "+f"(d[0]), "+f"(d[1]), "+f"(d[2]), "+f"(d[3])
                 : "r"(a[0]), "r"(a[1]), "r"(a[2]), "r"(a[3]), "r"(b[0]), "r"(b[1]));
}
__device__ __forceinline__ void cp16(uint32_t dst, const void* src) {
    asm volatile("cp.async.cg.shared.global [%0], [%1], 16;" :: "r"(dst), "l"(src));
}
#define CP_COMMIT() asm volatile("cp.async.commit_group;" ::: "memory")
#define CP_WAIT1()  asm volatile("cp.async.wait_group 1;" ::: "memory")

// ---------------- prep (proven) ----------------
__global__ __launch_bounds__(192)
void adjprep_kernel(const float* __restrict__ adj) {
    int row = blockIdx.x;
    int t   = threadIdx.x;
    const float4 v = ((const float4*)(adj + (size_t)row * NDIM))[t];
    float s = v.x + v.y + v.z + v.w;
    __shared__ float ws[6];
    __shared__ float rsh;
#pragma unroll
    for (int o = 16; o > 0; o >>= 1) s += __shfl_down_sync(0xffffffffu, s, o);
    if ((t & 31) == 0) ws[t >> 5] = s;
    __syncthreads();
    if (t == 0) {
        float tot = ws[0] + ws[1] + ws[2] + ws[3] + ws[4] + ws[5];
        rsh = (tot == 0.f) ? 0.f : (1.f / tot);
    }
    __syncthreads();
    float r = rsh;
    size_t base = (size_t)row * NDIM + t * 4;
    ((__half2*)(g_Adj + base))[0] = __floats2half2_rn(v.x * r, v.y * r);
    ((__half2*)(g_Adj + base))[1] = __floats2half2_rn(v.z * r, v.w * r);
}

__global__ __launch_bounds__(256)
void xhalf_kernel(const float* __restrict__ X) {
    size_t i = ((size_t)blockIdx.x * 256 + threadIdx.x) * 4;
    float4 v = *(const float4*)(X + i);
    size_t row = i / NDIM, col = i % NDIM;
    __half* d = g_XY + row * SXY + col;
    ((__half2*)d)[0] = __floats2half2_rn(v.x, v.y);
    ((__half2*)d)[1] = __floats2half2_rn(v.z, v.w);
}

__global__ __launch_bounds__(256)
void wcat_kernel(const float* __restrict__ W_l, const float* __restrict__ W_l1) {
    size_t i = ((size_t)blockIdx.x * 256 + threadIdx.x) * 4;
    {
        float4 v = *(const float4*)(W_l + i);
        ((__half2*)(g_Wcat + i))[0] = __floats2half2_rn(v.x, v.y);
        ((__half2*)(g_Wcat + i))[1] = __floats2half2_rn(v.z, v.w);
    }
    {
        float4 v = *(const float4*)(W_l1 + i);
        __half* d = g_Wcat + (size_t)NDIM * NDIM + i;
        ((__half2*)d)[0] = __floats2half2_rn(v.x, v.y);
        ((__half2*)d)[1] = __floats2half2_rn(v.z, v.w);
    }
}

// ---------------------------------------------------------------------------
// GEMM body: CTA 128x128, 256 thr, 8 warps (4m x 2n), warp 32x64, BK=64,
// 3 stages, 2-deep prefetch.  EPI 0: fp16 -> Yout; 1: lrelu fp32 -> Fout.
// ---------------------------------------------------------------------------
template<int NCH, int LDA, int LDB, int EPI>
__device__ __forceinline__ void gemm_body(
    const __half* __restrict__ A, const __half* __restrict__ B,
    __half* __restrict__ Yout, int ldy,
    float* __restrict__ Fout,
    int mb, int nb)
{
    extern __shared__ char sm[];
    const uint32_t smb = smem_u32(sm);

    const int tid  = threadIdx.x;
    const int lane = tid & 31;
    const int wid  = tid >> 5;
    const int wm   = wid >> 1;          // 0..3
    const int wn   = wid & 1;           // 0..1

    // cp mapping (BK=64): A row = tid>>1, half = (tid&1)*32 elems, 4x16B
    //                     B row = tid>>2, quarter = (tid&3)*32 elems, 4x16B
    const int ar  = tid >> 1;
    const int ak  = (tid & 1) * 32;
    const int bkr = tid >> 2;
    const int bn  = (tid & 3) * 32;

    auto issue = [&](int kt) {
        const uint32_t st = smb + (kt % 3) * S_BYTES;
        const size_t asrc = (size_t)(mb + ar) * LDA + kt * BK;
        const size_t bsrc = (size_t)(kt * BK + bkr) * LDB + nb;
#pragma unroll
        for (int c = 0; c < 4; c++) {
            int ko = ak + c * 8;
            cp16(st + S_AHI + (uint32_t)(ar * APAD + ko) * 2, A + asrc + ko);
            int no = bn + c * 8;
            cp16(st + S_BHI + (uint32_t)(bkr * BPAD + no) * 2, B + bsrc + no);
        }
        CP_COMMIT();
    };

    float acc[2][8][4];
#pragma unroll
    for (int i = 0; i < 2; i++)
#pragma unroll
        for (int j = 0; j < 8; j++)
#pragma unroll
            for (int q = 0; q < 4; q++) acc[i][j][q] = 0.f;

    issue(0);
    issue(1);

#pragma unroll 1
    for (int kt = 0; kt < NCH; kt++) {
        CP_WAIT1();
        __syncthreads();
        if (kt + 2 < NCH) issue(kt + 2); else CP_COMMIT();

        const uint32_t st = smb + (kt % 3) * S_BYTES;
#pragma unroll
        for (int ks = 0; ks < 4; ks++) {
            const int k0 = ks * 16;
            uint32_t a[2][4], bb[4][4];
#pragma unroll
            for (int m = 0; m < 2; m++)
                ldsm4(a[m], st + S_AHI + (uint32_t)((wm * 32 + m * 16 + (lane & 15)) * APAD
                                                    + k0 + (lane >> 4) * 8) * 2);
#pragma unroll
            for (int p = 0; p < 4; p++)
                ldsm4t(bb[p], st + S_BHI + (uint32_t)((k0 + (lane & 15)) * BPAD
                                                      + wn * 64 + p * 16 + (lane >> 4) * 8) * 2);
#pragma unroll
            for (int m = 0; m < 2; m++)
#pragma unroll
                for (int p = 0; p < 4; p++)
#pragma unroll
                    for (int h = 0; h < 2; h++)
                        hmma_f16(acc[m][p * 2 + h], a[m], &bb[p][h * 2]);
        }
    }

    const int row0 = mb + wm * 32 + (lane >> 2);
    const int col0 = nb + wn * 64 + (lane & 3) * 2;
    if (EPI == 0) {
#pragma unroll
        for (int m = 0; m < 2; m++)
#pragma unroll
            for (int ns = 0; ns < 8; ns++) {
                __half* c0 = Yout + (size_t)(row0 + m * 16) * ldy + col0 + ns * 8;
                __half* c1 = c0 + 8 * ldy;
                *(__half2*)c0 = __floats2half2_rn(acc[m][ns][0], acc[m][ns][1]);
                *(__half2*)c1 = __floats2half2_rn(acc[m][ns][2], acc[m][ns][3]);
            }
    } else {
#pragma unroll
        for (int m = 0; m < 2; m++)
#pragma unroll
            for (int ns = 0; ns < 8; ns++) {
                float h0 = acc[m][ns][0], h1 = acc[m][ns][1];
                float h2 = acc[m][ns][2], h3 = acc[m][ns][3];
                h0 = (h0 > 0.f) ? h0 : 0.01f * h0;
                h1 = (h1 > 0.f) ? h1 : 0.01f * h1;
                h2 = (h2 > 0.f) ? h2 : 0.01f * h2;
                h3 = (h3 > 0.f) ? h3 : 0.01f * h3;
                float* c0 = Fout + (size_t)(row0 + m * 16) * NDIM + col0 + ns * 8;
                float* c1 = c0 + 8 * NDIM;
                *(float2*)c0 = make_float2(h0, h1);
                *(float2*)c1 = make_float2(h2, h3);
            }
    }
}

// aggx: Y = adj_n @ X -> g_XY cols [768,1536).  grid (6, 6, 32)
__global__ __launch_bounds__(256, 2)
void aggx_kernel() {
    const int b  = blockIdx.z;
    const int nb = blockIdx.x * 128;
    const int mb = blockIdx.y * 128;
    const __half* A = g_Adj + (size_t)b * NDIM * NDIM;
    const __half* B = g_XY + (size_t)b * NDIM * SXY;
    __half* Y = g_XY + (size_t)b * NDIM * SXY + NDIM;
    gemm_body<NKT1, NDIM, SXY, 0>(A, B, Y, SXY, nullptr, mb, nb);
}

// biggemm: out = lrelu([X|Y] @ Wcat), K=1536.  grid (6, 192)
__global__ __launch_bounds__(256, 2)
void biggemm_kernel(float* __restrict__ out) {
    const int nb = blockIdx.x * 128;
    const int mb = blockIdx.y * 128;
    gemm_body<NKT_T, SXY, NDIM, 1>(g_XY, g_Wcat, nullptr, 0, out, mb, nb);
}

// ---------------------------------------------------------------------------
extern "C" void kernel_launch(void* const* d_in, const int* in_sizes, int n_in,
                              void* d_out, int out_size)
{
    const float* X    = (const float*)d_in[0];
    const float* adj  = (const float*)d_in[1];
    const float* W_l  = (const float*)d_in[2];
    const float* W_l1 = (const float*)d_in[3];
    float* out = (float*)d_out;

    cudaFuncSetAttribute(aggx_kernel,    cudaFuncAttributeMaxDynamicSharedMemorySize, SMEM_G);
    cudaFuncSetAttribute(biggemm_kernel, cudaFuncAttributeMaxDynamicSharedMemorySize, SMEM_G);

    adjprep_kernel<<<MTOT, 192>>>(adj);
    xhalf_kernel<<<(MTOT * NDIM) / 1024, 256>>>(X);
    wcat_kernel<<<(NDIM * NDIM) / 1024, 256>>>(W_l, W_l1);

    aggx_kernel<<<dim3(6, 6, 32), 256, SMEM_G>>>();
    biggemm_kernel<<<dim3(6, 192), 256, SMEM_G>>>(out);
}

// round 17
// speedup vs baseline: 1.1459x; 1.1459x over previous
#include <cuda_runtime.h>
#include <cuda_fp16.h>
#include <cstdint>

#define BATCH 32
#define NDIM  768
#define MTOT  (BATCH * NDIM)     // 24576
#define BK    32
#define NKT1  (NDIM / BK)        // 24 (aggx)
#define NKT_T (1536 / BK)        // 48 (biggemm, K=1536)
#define SXY   1536               // row stride of [X | Y]

#define N_AGG_ITEMS 1152         // 32 b x 6 my x 6 nx
#define N_BG_ITEMS  1152         // 192 mb128 x 6 nb
#define N_ITEMS     (N_AGG_ITEMS + N_BG_ITEMS)
#define N_FLAGS     192          // one per 128-row group of Y

// ---------------------------------------------------------------------------
// Scratch (fp16) + sync state
// ---------------------------------------------------------------------------
__device__ __half g_XY  [(size_t)MTOT * SXY];          // [X | Y] per row
__device__ __half g_Wcat[(size_t)1536 * NDIM];         // [W_l ; W_l1]
__device__ __half g_Adj [(size_t)BATCH * NDIM * NDIM]; // adj * rinv
__device__ int    g_ticket;
__device__ int    g_flag[N_FLAGS];

// ---------------------------------------------------------------------------
// smem geometry (R14-proven)
// ---------------------------------------------------------------------------
#define APAD 40
#define BPAD 136
#define A_BYTES (128 * APAD * 2)          // 10240
#define B_BYTES (BK * BPAD * 2)           // 8704
#define S_AHI 0
#define S_BHI (A_BYTES)
#define S_BYTES (A_BYTES + B_BYTES)       // 18944
#define SMEM_G (3 * S_BYTES)              // 56832 -> 2 CTAs/SM

// ---------------------------------------------------------------------------
// PTX helpers
// ---------------------------------------------------------------------------
__device__ __forceinline__ uint32_t smem_u32(const void* p) {
    uint32_t a;
    asm("{ .reg .u64 t; cvta.to.shared.u64 t, %1; cvt.u32.u64 %0, t; }" : "=r"(a) : "l"(p));
    return a;
}
__device__ __forceinline__ void ldsm4(uint32_t* r, uint32_t addr) {
    asm volatile("ldmatrix.sync.aligned.m8n8.x4.shared.b16 {%0,%1,%2,%3}, [%4];"
                 : "=r"(r[0]), "=r"(r[1]), "=r"(r[2]), "=r"(r[3]) : "r"(addr));
}
__device__ __forceinline__ void ldsm4t(uint32_t* r, uint32_t addr) {
    asm volatile("ldmatrix.sync.aligned.m8n8.x4.trans.shared.b16 {%0,%1,%2,%3}, [%4];"
                 : "=r"(r[0]), "=r"(r[1]), "=r"(r[2]), "=r"(r[3]) : "r"(addr));
}
__device__ __forceinline__ void hmma_f16(float* d, const uint32_t* a, const uint32_t* b) {
    asm volatile("mma.sync.aligned.m16n8k16.row.col.f32.f16.f16.f32 "
                 "{%0,%1,%2,%3}, {%4,%5,%6,%7}, {%8,%9}, {%0,%1,%2,%3};"
                 : "+f"(d[0]), "+f"(d[1]), "+f"(d[2]), "+f"(d[3])
                 : "r"(a[0]), "r"(a[1]), "r"(a[2]), "r"(a[3]), "r"(b[0]), "r"(b[1]));
}
__device__ __forceinline__ void cp16(uint32_t dst, const void* src) {
    asm volatile("cp.async.cg.shared.global [%0], [%1], 16;" :: "r"(dst), "l"(src));
}
#define CP_COMMIT() asm volatile("cp.async.commit_group;" ::: "memory")
#define CP_WAIT1()  asm volatile("cp.async.wait_group 1;" ::: "memory")

// ---------------- prep (R14-proven) ----------------
__global__ __launch_bounds__(192)
void adjprep_kernel(const float* __restrict__ adj) {
    int row = blockIdx.x;
    int t   = threadIdx.x;
    const float4 v = ((const float4*)(adj + (size_t)row * NDIM))[t];
    float s = v.x + v.y + v.z + v.w;
    __shared__ float ws[6];
    __shared__ float rsh;
#pragma unroll
    for (int o = 16; o > 0; o >>= 1) s += __shfl_down_sync(0xffffffffu, s, o);
    if ((t & 31) == 0) ws[t >> 5] = s;
    __syncthreads();
    if (t == 0) {
        float tot = ws[0] + ws[1] + ws[2] + ws[3] + ws[4] + ws[5];
        rsh = (tot == 0.f) ? 0.f : (1.f / tot);
    }
    __syncthreads();
    float r = rsh;
    size_t base = (size_t)row * NDIM + t * 4;
    ((__half2*)(g_Adj + base))[0] = __floats2half2_rn(v.x * r, v.y * r);
    ((__half2*)(g_Adj + base))[1] = __floats2half2_rn(v.z * r, v.w * r);
}

__global__ __launch_bounds__(256)
void xhalf_kernel(const float* __restrict__ X) {
    size_t i = ((size_t)blockIdx.x * 256 + threadIdx.x) * 4;
    float4 v = *(const float4*)(X + i);
    size_t row = i / NDIM, col = i % NDIM;
    __half* d = g_XY + row * SXY + col;
    ((__half2*)d)[0] = __floats2half2_rn(v.x, v.y);
    ((__half2*)d)[1] = __floats2half2_rn(v.z, v.w);
}

__global__ __launch_bounds__(256)
void wcat_kernel(const float* __restrict__ W_l, const float* __restrict__ W_l1) {
    size_t i = ((size_t)blockIdx.x * 256 + threadIdx.x) * 4;
    {
        float4 v = *(const float4*)(W_l + i);
        ((__half2*)(g_Wcat + i))[0] = __floats2half2_rn(v.x, v.y);
        ((__half2*)(g_Wcat + i))[1] = __floats2half2_rn(v.z, v.w);
    }
    {
        float4 v = *(const float4*)(W_l1 + i);
        __half* d = g_Wcat + (size_t)NDIM * NDIM + i;
        ((__half2*)d)[0] = __floats2half2_rn(v.x, v.y);
        ((__half2*)d)[1] = __floats2half2_rn(v.z, v.w);
    }
}

// reset ticket + flags (every launch; graph-replay safe)
__global__ void init_kernel() {
    if (threadIdx.x == 0) g_ticket = 0;
    if (threadIdx.x < N_FLAGS) g_flag[threadIdx.x] = 0;
}

// ---------------------------------------------------------------------------
// GEMM tile body (R14-proven geometry). waitflag: if non-null, spin until
// *waitflag == 6 before issuing chunk 24 (Y-dependent chunks).
// EPI 0: fp16 -> Yout (ldy stride); EPI 1: lrelu fp32 -> Fout.
// ---------------------------------------------------------------------------
template<int NCH, int LDA, int LDB, int EPI>
__device__ __forceinline__ void gemm_body(
    const __half* __restrict__ A, const __half* __restrict__ B,
    __half* __restrict__ Yout, int ldy,
    float* __restrict__ Fout,
    int mb, int nb,
    volatile int* waitflag)
{
    extern __shared__ char sm[];
    const uint32_t smb = smem_u32(sm);

    const int tid  = threadIdx.x;
    const int lane = tid & 31;
    const int wid  = tid >> 5;
    const int wm   = wid >> 1;
    const int wn   = wid & 1;
    const int ar  = tid >> 1;
    const int ak  = (tid & 1) * 16;
    const int bkr = tid >> 3;
    const int bn  = (tid & 7) * 16;

    auto issue = [&](int kt) {
        const uint32_t st = smb + (kt % 3) * S_BYTES;
        const size_t asrc = (size_t)(mb + ar) * LDA + kt * BK;
        const size_t bsrc = (size_t)(kt * BK + bkr) * LDB + nb;
#pragma unroll
        for (int c = 0; c < 2; c++) {
            int ko = ak + c * 8;
            cp16(st + S_AHI + (uint32_t)(ar * APAD + ko) * 2, A + asrc + ko);
            int no = bn + c * 8;
            cp16(st + S_BHI + (uint32_t)(bkr * BPAD + no) * 2, B + bsrc + no);
        }
        CP_COMMIT();
    };

    float acc[2][8][4];
#pragma unroll
    for (int i = 0; i < 2; i++)
#pragma unroll
        for (int j = 0; j < 8; j++)
#pragma unroll
            for (int q = 0; q < 4; q++) acc[i][j][q] = 0.f;

    issue(0);
    issue(1);

#pragma unroll 1
    for (int kt = 0; kt < NCH; kt++) {
        CP_WAIT1();
        __syncthreads();
        // dependency gate: chunk 24+ reads Y; spin before issuing chunk 24
        if (NCH > 24 && waitflag != nullptr && kt == 22) {
            if (tid == 0) {
                while (*waitflag < 6) __nanosleep(200);
            }
            __syncthreads();
            __threadfence();   // acquire: order subsequent reads after flag
        }
        if (kt + 2 < NCH) issue(kt + 2); else CP_COMMIT();

        const uint32_t st = smb + (kt % 3) * S_BYTES;
#pragma unroll
        for (int ks = 0; ks < 2; ks++) {
            const int k0 = ks * 16;
            uint32_t a[2][4], bb[4][4];
#pragma unroll
            for (int m = 0; m < 2; m++)
                ldsm4(a[m], st + S_AHI + (uint32_t)((wm * 32 + m * 16 + (lane & 15)) * APAD
                                                    + k0 + (lane >> 4) * 8) * 2);
#pragma unroll
            for (int p = 0; p < 4; p++)
                ldsm4t(bb[p], st + S_BHI + (uint32_t)((k0 + (lane & 15)) * BPAD
                                                      + wn * 64 + p * 16 + (lane >> 4) * 8) * 2);
#pragma unroll
            for (int m = 0; m < 2; m++)
#pragma unroll
                for (int p = 0; p < 4; p++)
#pragma unroll
                    for (int h = 0; h < 2; h++)
                        hmma_f16(acc[m][p * 2 + h], a[m], &bb[p][h * 2]);
        }
    }

    const int row0 = mb + wm * 32 + (lane >> 2);
    const int col0 = nb + wn * 64 + (lane & 3) * 2;
    if (EPI == 0) {
#pragma unroll
        for (int m = 0; m < 2; m++)
#pragma unroll
            for (int ns = 0; ns < 8; ns++) {
                __half* c0 = Yout + (size_t)(row0 + m * 16) * ldy + col0 + ns * 8;
                __half* c1 = c0 + 8 * ldy;
                *(__half2*)c0 = __floats2half2_rn(acc[m][ns][0], acc[m][ns][1]);
                *(__half2*)c1 = __floats2half2_rn(acc[m][ns][2], acc[m][ns][3]);
            }
    } else {
#pragma unroll
        for (int m = 0; m < 2; m++)
#pragma unroll
            for (int ns = 0; ns < 8; ns++) {
                float h0 = acc[m][ns][0], h1 = acc[m][ns][1];
                float h2 = acc[m][ns][2], h3 = acc[m][ns][3];
                h0 = (h0 > 0.f) ? h0 : 0.01f * h0;
                h1 = (h1 > 0.f) ? h1 : 0.01f * h1;
                h2 = (h2 > 0.f) ? h2 : 0.01f * h2;
                h3 = (h3 > 0.f) ? h3 : 0.01f * h3;
                float* c0 = Fout + (size_t)(row0 + m * 16) * NDIM + col0 + ns * 8;
                float* c1 = c0 + 8 * NDIM;
                *(float2*)c0 = make_float2(h0, h1);
                *(float2*)c1 = make_float2(h2, h3);
            }
    }
}

// ---------------------------------------------------------------------------
// Fused persistent kernel: work queue of 1152 aggx tiles then 1152 biggemm tiles
// ---------------------------------------------------------------------------
__global__ __launch_bounds__(256, 2)
void fused_kernel(float* __restrict__ out) {
    __shared__ int s_item;
    const int tid = threadIdx.x;

    for (;;) {
        __syncthreads();                       // protect s_item reuse
        if (tid == 0) s_item = atomicAdd(&g_ticket, 1);
        __syncthreads();
        const int item = s_item;
        if (item >= N_ITEMS) return;

        if (item < N_AGG_ITEMS) {
            // aggx tile: Y[b][my*128: , nx*128:] = adj_n(b) @ X(b)
            const int b  = item / 36;
            const int r  = item % 36;
            const int my = r / 6;
            const int nx = r % 6;
            const int mb = my * 128;
            const int nb = nx * 128;
            const __half* A = g_Adj + (size_t)b * NDIM * NDIM;
            const __half* B = g_XY + (size_t)b * NDIM * SXY;
            __half* Y = g_XY + (size_t)b * NDIM * SXY + NDIM;
            gemm_body<NKT1, NDIM, SXY, 0>(A, B, Y, SXY, nullptr, mb, nb, nullptr);
            __threadfence();                   // all threads: publish Y stores
            __syncthreads();
            if (tid == 0) atomicAdd(&g_flag[b * 6 + my], 1);
        } else {
            // biggemm tile: out[mb128*128: , nb:] = lrelu([X|Y] @ Wcat)
            const int r     = item - N_AGG_ITEMS;
            const int mb128 = r / 6;           // == flag index
            const int nb    = (r % 6) * 128;
            const int mb    = mb128 * 128;
            gemm_body<NKT_T, SXY, NDIM, 1>(g_XY, g_Wcat, nullptr, 0, out,
                                           mb, nb, (volatile int*)&g_flag[mb128]);
        }
    }
}

// ---------------------------------------------------------------------------
extern "C" void kernel_launch(void* const* d_in, const int* in_sizes, int n_in,
                              void* d_out, int out_size)
{
    const float* X    = (const float*)d_in[0];
    const float* adj  = (const float*)d_in[1];
    const float* W_l  = (const float*)d_in[2];
    const float* W_l1 = (const float*)d_in[3];
    float* out = (float*)d_out;

    cudaFuncSetAttribute(fused_kernel, cudaFuncAttributeMaxDynamicSharedMemorySize, SMEM_G);

    init_kernel<<<1, 256>>>();
    adjprep_kernel<<<MTOT, 192>>>(adj);
    xhalf_kernel<<<(MTOT * NDIM) / 1024, 256>>>(X);
    wcat_kernel<<<(NDIM * NDIM) / 1024, 256>>>(W_l, W_l1);

    fused_kernel<<<296, 256, SMEM_G>>>(out);
}